// round 1
// baseline (speedup 1.0000x reference)
#include <cuda_runtime.h>
#include <cuda_bf16.h>

#define NN 100000
#define EE 1600000
#define DIM 128
#define NH 4
#define HD 32

// ---------------- device scratch (static — no allocation allowed) ----------------
__device__ float g_h[(size_t)NN * DIM];      // projected features [N,128]
__device__ float g_esrc[NN * NH];            // per-node src logits [N,4]
__device__ float g_edst[NN * NH];            // per-node dst logits [N,4]
__device__ int   g_deg[NN];
__device__ int   g_cur[NN];
__device__ int   g_off[NN + 1];
__device__ int   g_edge_src[EE];             // src ids grouped by dst (CSR)
__device__ int   g_is64;

// ---------------- helpers ----------------
__device__ __forceinline__ int edge_idx(const void* p, int i, int is64) {
    return is64 ? (int)((const long long*)p)[i] : ((const int*)p)[i];
}

// detect whether src/dst are int64 (high 32-bit words all zero) or int32
__global__ void k_detect(const void* src) {
    const unsigned* p = (const unsigned*)src;
    int is64 = 1;
    for (int j = 0; j < 64; j++) {
        if (p[2 * j + 1] != 0u) { is64 = 0; break; }
    }
    g_is64 = is64;
}

__global__ void k_init() {
    int i = blockIdx.x * blockDim.x + threadIdx.x;
    if (i < NN) { g_deg[i] = 0; g_cur[i] = 0; }
}

// ---------------- GEMM: h = feat @ fc_w.T  (N x 128 @ 128 x 128) ----------------
// block = 256 threads, 64 rows x 128 cols per block. Thread: 4 cols x 8 rows.
#define KC 32
__global__ void __launch_bounds__(256) k_gemm(const float* __restrict__ feat,
                                              const float* __restrict__ fc_w) {
    __shared__ float wT[KC][132];   // [k][col], padded to keep float4 align + no read conflicts
    __shared__ float fT[KC][68];    // [k][row]
    int tid = threadIdx.x;
    int tx = tid & 31;              // col group: cols 4*tx..4*tx+3
    int ty = tid >> 5;              // row group: rows ty*8..ty*8+7 within block
    int rbase = blockIdx.x * 64;

    float4 acc[8];
#pragma unroll
    for (int r = 0; r < 8; r++) acc[r] = make_float4(0.f, 0.f, 0.f, 0.f);

    for (int k0 = 0; k0 < DIM; k0 += KC) {
        __syncthreads();
        // stage fc_w chunk transposed: 128 cols x 32 k = 1024 float4 loads / 256 thr
#pragma unroll
        for (int q = 0; q < 4; q++) {
            int id = tid + q * 256;           // 0..1023
            int c  = id >> 3;                 // 0..127
            int ks = (id & 7) * 4;            // 0..28
            float4 v = *(const float4*)&fc_w[c * DIM + k0 + ks];
            wT[ks + 0][c] = v.x; wT[ks + 1][c] = v.y;
            wT[ks + 2][c] = v.z; wT[ks + 3][c] = v.w;
        }
        // stage feat chunk transposed: 64 rows x 32 k = 512 float4 / 256 thr
#pragma unroll
        for (int q = 0; q < 2; q++) {
            int id = tid + q * 256;           // 0..511
            int r  = id >> 3;                 // 0..63
            int ks = (id & 7) * 4;
            int gr = rbase + r;
            float4 v = make_float4(0.f, 0.f, 0.f, 0.f);
            if (gr < NN) v = *(const float4*)&feat[(size_t)gr * DIM + k0 + ks];
            fT[ks + 0][r] = v.x; fT[ks + 1][r] = v.y;
            fT[ks + 2][r] = v.z; fT[ks + 3][r] = v.w;
        }
        __syncthreads();
#pragma unroll
        for (int kk = 0; kk < KC; kk++) {
            float4 w  = *(const float4*)&wT[kk][tx * 4];
            float4 fa = *(const float4*)&fT[kk][ty * 8];
            float4 fb = *(const float4*)&fT[kk][ty * 8 + 4];
#define FMA4(A, S) A.x += (S) * w.x; A.y += (S) * w.y; A.z += (S) * w.z; A.w += (S) * w.w;
            FMA4(acc[0], fa.x) FMA4(acc[1], fa.y) FMA4(acc[2], fa.z) FMA4(acc[3], fa.w)
            FMA4(acc[4], fb.x) FMA4(acc[5], fb.y) FMA4(acc[6], fb.z) FMA4(acc[7], fb.w)
#undef FMA4
        }
    }
#pragma unroll
    for (int r = 0; r < 8; r++) {
        int gr = rbase + ty * 8 + r;
        if (gr < NN) *(float4*)&g_h[(size_t)gr * DIM + tx * 4] = acc[r];
    }
}

// ---------------- per-node attention logits ----------------
// warp per node: e_src[n][h] = sum_d h[n][h][d]*attn_src[h][d]
__global__ void __launch_bounds__(256) k_logits(const float* __restrict__ attn_src,
                                                const float* __restrict__ attn_dst) {
    int warp = (blockIdx.x * blockDim.x + threadIdx.x) >> 5;
    int lane = threadIdx.x & 31;
    if (warp >= NN) return;
    float4 h4 = *(const float4*)&g_h[(size_t)warp * DIM + lane * 4];
    float4 as = *(const float4*)&attn_src[lane * 4];
    float4 ad = *(const float4*)&attn_dst[lane * 4];
    float ps = h4.x * as.x + h4.y * as.y + h4.z * as.z + h4.w * as.w;
    float pd = h4.x * ad.x + h4.y * ad.y + h4.z * ad.z + h4.w * ad.w;
#pragma unroll
    for (int o = 1; o < 8; o <<= 1) {
        ps += __shfl_xor_sync(0xffffffffu, ps, o);
        pd += __shfl_xor_sync(0xffffffffu, pd, o);
    }
    if ((lane & 7) == 0) {
        int head = lane >> 3;
        g_esrc[warp * NH + head] = ps;
        g_edst[warp * NH + head] = pd;
    }
}

// ---------------- CSR build ----------------
__global__ void k_hist(const void* __restrict__ dst) {
    int i = blockIdx.x * blockDim.x + threadIdx.x;
    if (i >= EE) return;
    int is64 = g_is64;
    int d = edge_idx(dst, i, is64);
    atomicAdd(&g_deg[d], 1);
}

__global__ void __launch_bounds__(1024) k_scan() {
    __shared__ int sm[1024];
    int t = threadIdx.x;
    const int C = 98;                 // 1024*98 = 100352 >= 100000
    int base = t * C;
    int local = 0;
    for (int j = 0; j < C; j++) {
        int idx = base + j;
        if (idx < NN) local += g_deg[idx];
    }
    sm[t] = local;
    __syncthreads();
    for (int off = 1; off < 1024; off <<= 1) {
        int v = (t >= off) ? sm[t - off] : 0;
        __syncthreads();
        sm[t] += v;
        __syncthreads();
    }
    int run = sm[t] - local;          // exclusive prefix
    for (int j = 0; j < C; j++) {
        int idx = base + j;
        if (idx < NN) { g_off[idx] = run; run += g_deg[idx]; }
    }
    if (t == 1023) g_off[NN] = sm[1023];
}

__global__ void k_scatter(const void* __restrict__ src, const void* __restrict__ dst) {
    int i = blockIdx.x * blockDim.x + threadIdx.x;
    if (i >= EE) return;
    int is64 = g_is64;
    int d = edge_idx(dst, i, is64);
    int s = edge_idx(src, i, is64);
    int pos = g_off[d] + atomicAdd(&g_cur[d], 1);
    g_edge_src[pos] = s;
}

// ---------------- softmax + aggregation: warp per dst node ----------------
__global__ void __launch_bounds__(256) k_agg(const float* __restrict__ feat,
                                             float* __restrict__ out) {
    int n = (blockIdx.x * blockDim.x + threadIdx.x) >> 5;
    int lane = threadIdx.x & 31;
    if (n >= NN) return;
    int beg = g_off[n], end = g_off[n + 1];
    float4 f4 = *(const float4*)&feat[(size_t)n * DIM + lane * 4];
    if (beg == end) {                 // no incoming edges: out = feat (residual)
        *(float4*)&out[(size_t)n * DIM + lane * 4] = f4;
        return;
    }
    float4 ed4 = *(const float4*)&g_edst[n * NH];

    // phase 1: sum of exp(leaky(e)) per head (no max-sub; |e| <~ 5, safe in fp32)
    float4 s4 = make_float4(0.f, 0.f, 0.f, 0.f);
    for (int i = beg + lane; i < end; i += 32) {
        int s = g_edge_src[i];
        float4 es = *(const float4*)&g_esrc[s * NH];
        float ex = es.x + ed4.x; ex = ex > 0.f ? ex : 0.2f * ex;
        float ey = es.y + ed4.y; ey = ey > 0.f ? ey : 0.2f * ey;
        float ez = es.z + ed4.z; ez = ez > 0.f ? ez : 0.2f * ez;
        float ew = es.w + ed4.w; ew = ew > 0.f ? ew : 0.2f * ew;
        s4.x += __expf(ex); s4.y += __expf(ey);
        s4.z += __expf(ez); s4.w += __expf(ew);
    }
#pragma unroll
    for (int o = 1; o < 32; o <<= 1) {
        s4.x += __shfl_xor_sync(0xffffffffu, s4.x, o);
        s4.y += __shfl_xor_sync(0xffffffffu, s4.y, o);
        s4.z += __shfl_xor_sync(0xffffffffu, s4.z, o);
        s4.w += __shfl_xor_sync(0xffffffffu, s4.w, o);
    }
    int head = lane >> 3;             // this lane's 4 dims all belong to one head
    float ssum = (head == 0) ? s4.x : (head == 1) ? s4.y : (head == 2) ? s4.z : s4.w;
    float edh  = (head == 0) ? ed4.x : (head == 1) ? ed4.y : (head == 2) ? ed4.z : ed4.w;
    float inv = 1.0f / ssum;

    // phase 2: gather h[src] weighted by unnormalized exp, normalize at the end
    float4 acc = make_float4(0.f, 0.f, 0.f, 0.f);
    for (int i = beg; i < end; i++) {
        int s = g_edge_src[i];        // warp-uniform
        float e = g_esrc[s * NH + head] + edh;
        e = e > 0.f ? e : 0.2f * e;
        float w = __expf(e);
        float4 hv = *(const float4*)&g_h[(size_t)s * DIM + lane * 4];
        acc.x += w * hv.x; acc.y += w * hv.y;
        acc.z += w * hv.z; acc.w += w * hv.w;
    }
    float4 o4;
    o4.x = acc.x * inv + f4.x;
    o4.y = acc.y * inv + f4.y;
    o4.z = acc.z * inv + f4.z;
    o4.w = acc.w * inv + f4.w;
    *(float4*)&out[(size_t)n * DIM + lane * 4] = o4;
}

// ---------------- launch ----------------
extern "C" void kernel_launch(void* const* d_in, const int* in_sizes, int n_in,
                              void* d_out, int out_size) {
    const float* feat     = (const float*)d_in[0];
    const float* fc_w     = (const float*)d_in[1];
    const float* attn_src = (const float*)d_in[2];
    const float* attn_dst = (const float*)d_in[3];
    const void*  src      = d_in[4];
    const void*  dst      = d_in[5];
    float* out = (float*)d_out;

    k_detect<<<1, 1>>>(src);
    k_init<<<(NN + 255) / 256, 256>>>();
    k_gemm<<<(NN + 63) / 64, 256>>>(feat, fc_w);
    k_logits<<<(NN + 7) / 8, 256>>>(attn_src, attn_dst);
    k_hist<<<(EE + 255) / 256, 256>>>(dst);
    k_scan<<<1, 1024>>>();
    k_scatter<<<(EE + 255) / 256, 256>>>(src, dst);
    k_agg<<<(NN + 7) / 8, 256>>>(feat, out);
}

// round 2
// speedup vs baseline: 1.0470x; 1.0470x over previous
#include <cuda_runtime.h>
#include <cuda_bf16.h>

#define NN 100000
#define EE 1600000
#define DIM 128
#define NH 4
#define HD 32

// ---------------- device scratch (static — no allocation allowed) ----------------
__device__ float g_h[(size_t)NN * DIM];      // projected features [N,128]
__device__ float g_esrc[NN * NH];            // per-node src logits [N,4]
__device__ float g_edst[NN * NH];            // per-node dst logits [N,4]
__device__ int   g_deg[NN];
__device__ int   g_cur[NN];
__device__ int   g_off[NN + 1];
__device__ int   g_edge_src[EE];             // src ids grouped by dst (CSR)
__device__ int   g_is64;

// ---------------- f32x2 helpers (Blackwell packed fp32 — PTX only) ----------------
__device__ __forceinline__ unsigned long long pk2(float s) {
    unsigned long long d;
    asm("mov.b64 %0, {%1, %1};" : "=l"(d) : "f"(s));
    return d;
}
__device__ __forceinline__ void fma2(unsigned long long& c, unsigned long long a,
                                     unsigned long long b) {
    asm("fma.rn.f32x2 %0, %1, %2, %0;" : "+l"(c) : "l"(a), "l"(b));
}
__device__ __forceinline__ float2 up2(unsigned long long v) {
    float2 r;
    asm("mov.b64 {%0, %1}, %2;" : "=f"(r.x), "=f"(r.y) : "l"(v));
    return r;
}

// ---------------- helpers ----------------
__device__ __forceinline__ int edge_idx(const void* p, int i, int is64) {
    return is64 ? (int)((const long long*)p)[i] : ((const int*)p)[i];
}

// detect whether src/dst are int64 (high 32-bit words all zero) or int32
__global__ void k_detect(const void* src) {
    const unsigned* p = (const unsigned*)src;
    int is64 = 1;
    for (int j = 0; j < 64; j++) {
        if (p[2 * j + 1] != 0u) { is64 = 0; break; }
    }
    g_is64 = is64;
}

__global__ void k_init() {
    int i = blockIdx.x * blockDim.x + threadIdx.x;
    if (i < NN) { g_deg[i] = 0; g_cur[i] = 0; }
}

// ---------------- GEMM + fused logits ----------------
// h = feat @ fc_w.T  (N x 128 @ 128 x 128), then e_src/e_dst per row.
// block = 256 threads, 64 rows x 128 cols per block. Thread: 4 cols x 8 rows.
// Mainloop uses packed fma.rn.f32x2 (2x fp32 rate on sm_103a).
#define KC 32
__global__ void __launch_bounds__(256) k_gemm(const float* __restrict__ feat,
                                              const float* __restrict__ fc_w,
                                              const float* __restrict__ attn_src,
                                              const float* __restrict__ attn_dst) {
    __shared__ float wT[KC][132];   // [k][col], padded: row stride 528B (16B-mult)
    __shared__ float fT[KC][68];    // [k][row], row stride 272B (16B-mult)
    int tid = threadIdx.x;
    int tx = tid & 31;              // lane: cols 4*tx..4*tx+3
    int ty = tid >> 5;              // warp: rows ty*8..ty*8+7 within block
    int rbase = blockIdx.x * 64;

    unsigned long long A[16];       // 8 rows x 2 f32x2 pairs (cols 4tx..4tx+3)
#pragma unroll
    for (int r = 0; r < 16; r++) A[r] = 0ull;

    for (int k0 = 0; k0 < DIM; k0 += KC) {
        __syncthreads();
        // stage fc_w chunk transposed: 128 cols x 32 k
#pragma unroll
        for (int q = 0; q < 4; q++) {
            int id = tid + q * 256;           // 0..1023
            int c  = id >> 3;                 // 0..127
            int ks = (id & 7) * 4;            // 0..28
            float4 v = *(const float4*)&fc_w[c * DIM + k0 + ks];
            wT[ks + 0][c] = v.x; wT[ks + 1][c] = v.y;
            wT[ks + 2][c] = v.z; wT[ks + 3][c] = v.w;
        }
        // stage feat chunk transposed: 64 rows x 32 k
#pragma unroll
        for (int q = 0; q < 2; q++) {
            int id = tid + q * 256;           // 0..511
            int r  = id >> 3;                 // 0..63
            int ks = (id & 7) * 4;
            int gr = rbase + r;
            float4 v = make_float4(0.f, 0.f, 0.f, 0.f);
            if (gr < NN) v = *(const float4*)&feat[(size_t)gr * DIM + k0 + ks];
            fT[ks + 0][r] = v.x; fT[ks + 1][r] = v.y;
            fT[ks + 2][r] = v.z; fT[ks + 3][r] = v.w;
        }
        __syncthreads();
#pragma unroll
        for (int kk = 0; kk < KC; kk++) {
            ulonglong2 w2 = *(const ulonglong2*)&wT[kk][tx * 4];   // (wx,wy),(wz,ww)
            float4 fa = *(const float4*)&fT[kk][ty * 8];
            float4 fb = *(const float4*)&fT[kk][ty * 8 + 4];
#define STEP(r, S) { unsigned long long b = pk2(S); \
                     fma2(A[2*(r)], w2.x, b); fma2(A[2*(r)+1], w2.y, b); }
            STEP(0, fa.x) STEP(1, fa.y) STEP(2, fa.z) STEP(3, fa.w)
            STEP(4, fb.x) STEP(5, fb.y) STEP(6, fb.z) STEP(7, fb.w)
#undef STEP
        }
    }

    // attn vectors for this lane's 4 cols (all 4 cols belong to head tx>>3)
    float4 as4 = *(const float4*)&attn_src[tx * 4];
    float4 ad4 = *(const float4*)&attn_dst[tx * 4];
    int head = tx >> 3;

#pragma unroll
    for (int r = 0; r < 8; r++) {
        int gr = rbase + ty * 8 + r;
        float2 p0 = up2(A[2 * r]);
        float2 p1 = up2(A[2 * r + 1]);
        if (gr < NN) {
            float4 o; o.x = p0.x; o.y = p0.y; o.z = p1.x; o.w = p1.y;
            *(float4*)&g_h[(size_t)gr * DIM + tx * 4] = o;
        }
        // fused logits: per-head dot across lanes 8h..8h+7
        float ps = p0.x * as4.x + p0.y * as4.y + p1.x * as4.z + p1.y * as4.w;
        float pd = p0.x * ad4.x + p0.y * ad4.y + p1.x * ad4.z + p1.y * ad4.w;
#pragma unroll
        for (int o = 1; o < 8; o <<= 1) {
            ps += __shfl_xor_sync(0xffffffffu, ps, o);
            pd += __shfl_xor_sync(0xffffffffu, pd, o);
        }
        if (gr < NN && (tx & 7) == 0) {
            g_esrc[gr * NH + head] = ps;
            g_edst[gr * NH + head] = pd;
        }
    }
}

// ---------------- CSR build ----------------
__global__ void k_hist(const void* __restrict__ dst) {
    int i = blockIdx.x * blockDim.x + threadIdx.x;
    if (i >= EE) return;
    int is64 = g_is64;
    int d = edge_idx(dst, i, is64);
    atomicAdd(&g_deg[d], 1);
}

__global__ void __launch_bounds__(1024) k_scan() {
    __shared__ int sm[1024];
    int t = threadIdx.x;
    const int C = 98;                 // 1024*98 = 100352 >= 100000
    int base = t * C;
    int local = 0;
    for (int j = 0; j < C; j++) {
        int idx = base + j;
        if (idx < NN) local += g_deg[idx];
    }
    sm[t] = local;
    __syncthreads();
    for (int off = 1; off < 1024; off <<= 1) {
        int v = (t >= off) ? sm[t - off] : 0;
        __syncthreads();
        sm[t] += v;
        __syncthreads();
    }
    int run = sm[t] - local;          // exclusive prefix
    for (int j = 0; j < C; j++) {
        int idx = base + j;
        if (idx < NN) { g_off[idx] = run; run += g_deg[idx]; }
    }
    if (t == 1023) g_off[NN] = sm[1023];
}

__global__ void k_scatter(const void* __restrict__ src, const void* __restrict__ dst) {
    int i = blockIdx.x * blockDim.x + threadIdx.x;
    if (i >= EE) return;
    int is64 = g_is64;
    int d = edge_idx(dst, i, is64);
    int s = edge_idx(src, i, is64);
    int pos = g_off[d] + atomicAdd(&g_cur[d], 1);
    g_edge_src[pos] = s;
}

// ---------------- softmax + aggregation: warp per dst node ----------------
__global__ void __launch_bounds__(256) k_agg(const float* __restrict__ feat,
                                             float* __restrict__ out) {
    int n = (blockIdx.x * blockDim.x + threadIdx.x) >> 5;
    int lane = threadIdx.x & 31;
    if (n >= NN) return;
    int beg = g_off[n], end = g_off[n + 1];
    float4 f4 = *(const float4*)&feat[(size_t)n * DIM + lane * 4];
    if (beg == end) {                 // no incoming edges: out = feat (residual)
        *(float4*)&out[(size_t)n * DIM + lane * 4] = f4;
        return;
    }
    float4 ed4 = *(const float4*)&g_edst[n * NH];

    // phase 1: sum of exp(leaky(e)) per head (no max-sub; |e| <~ 5, safe in fp32)
    float4 s4 = make_float4(0.f, 0.f, 0.f, 0.f);
    for (int i = beg + lane; i < end; i += 32) {
        int s = g_edge_src[i];
        float4 es = *(const float4*)&g_esrc[s * NH];
        float ex = es.x + ed4.x; ex = ex > 0.f ? ex : 0.2f * ex;
        float ey = es.y + ed4.y; ey = ey > 0.f ? ey : 0.2f * ey;
        float ez = es.z + ed4.z; ez = ez > 0.f ? ez : 0.2f * ez;
        float ew = es.w + ed4.w; ew = ew > 0.f ? ew : 0.2f * ew;
        s4.x += __expf(ex); s4.y += __expf(ey);
        s4.z += __expf(ez); s4.w += __expf(ew);
    }
#pragma unroll
    for (int o = 1; o < 32; o <<= 1) {
        s4.x += __shfl_xor_sync(0xffffffffu, s4.x, o);
        s4.y += __shfl_xor_sync(0xffffffffu, s4.y, o);
        s4.z += __shfl_xor_sync(0xffffffffu, s4.z, o);
        s4.w += __shfl_xor_sync(0xffffffffu, s4.w, o);
    }
    int head = lane >> 3;             // this lane's 4 dims all belong to one head
    float ssum = (head == 0) ? s4.x : (head == 1) ? s4.y : (head == 2) ? s4.z : s4.w;
    float edh  = (head == 0) ? ed4.x : (head == 1) ? ed4.y : (head == 2) ? ed4.z : ed4.w;
    float inv = 1.0f / ssum;

    // phase 2: gather h[src] weighted by unnormalized exp, 2-way unrolled for MLP
    float4 acc = make_float4(0.f, 0.f, 0.f, 0.f);
    int i = beg;
    for (; i + 2 <= end; i += 2) {
        int s0 = g_edge_src[i];
        int s1 = g_edge_src[i + 1];
        float e0 = g_esrc[s0 * NH + head] + edh;
        float e1 = g_esrc[s1 * NH + head] + edh;
        float4 h0 = *(const float4*)&g_h[(size_t)s0 * DIM + lane * 4];
        float4 h1 = *(const float4*)&g_h[(size_t)s1 * DIM + lane * 4];
        e0 = e0 > 0.f ? e0 : 0.2f * e0;
        e1 = e1 > 0.f ? e1 : 0.2f * e1;
        float w0 = __expf(e0);
        float w1 = __expf(e1);
        acc.x += w0 * h0.x; acc.y += w0 * h0.y;
        acc.z += w0 * h0.z; acc.w += w0 * h0.w;
        acc.x += w1 * h1.x; acc.y += w1 * h1.y;
        acc.z += w1 * h1.z; acc.w += w1 * h1.w;
    }
    for (; i < end; i++) {
        int s = g_edge_src[i];
        float e = g_esrc[s * NH + head] + edh;
        e = e > 0.f ? e : 0.2f * e;
        float w = __expf(e);
        float4 hv = *(const float4*)&g_h[(size_t)s * DIM + lane * 4];
        acc.x += w * hv.x; acc.y += w * hv.y;
        acc.z += w * hv.z; acc.w += w * hv.w;
    }
    float4 o4;
    o4.x = acc.x * inv + f4.x;
    o4.y = acc.y * inv + f4.y;
    o4.z = acc.z * inv + f4.z;
    o4.w = acc.w * inv + f4.w;
    *(float4*)&out[(size_t)n * DIM + lane * 4] = o4;
}

// ---------------- launch ----------------
extern "C" void kernel_launch(void* const* d_in, const int* in_sizes, int n_in,
                              void* d_out, int out_size) {
    const float* feat     = (const float*)d_in[0];
    const float* fc_w     = (const float*)d_in[1];
    const float* attn_src = (const float*)d_in[2];
    const float* attn_dst = (const float*)d_in[3];
    const void*  src      = d_in[4];
    const void*  dst      = d_in[5];
    float* out = (float*)d_out;

    // one-time host-side stream/event setup (first call = correctness run, not captured)
    static cudaStream_t s2 = nullptr;
    static cudaEvent_t evA = nullptr, evB = nullptr;
    if (!s2) {
        cudaStreamCreate(&s2);
        cudaEventCreateWithFlags(&evA, cudaEventDisableTiming);
        cudaEventCreateWithFlags(&evB, cudaEventDisableTiming);
    }

    // fork: CSR build chain on s2 (depends only on src/dst), GEMM on main stream
    cudaEventRecord(evA, 0);
    cudaStreamWaitEvent(s2, evA, 0);

    k_detect<<<1, 1, 0, s2>>>(src);
    k_init<<<(NN + 255) / 256, 256, 0, s2>>>();
    k_hist<<<(EE + 255) / 256, 256, 0, s2>>>(dst);
    k_scan<<<1, 1024, 0, s2>>>();
    k_scatter<<<(EE + 255) / 256, 256, 0, s2>>>(src, dst);
    cudaEventRecord(evB, s2);

    k_gemm<<<(NN + 63) / 64, 256>>>(feat, fc_w, attn_src, attn_dst);

    // join, then aggregate
    cudaStreamWaitEvent(0, evB, 0);
    k_agg<<<(NN + 7) / 8, 256>>>(feat, out);
}

// round 4
// speedup vs baseline: 1.5575x; 1.4876x over previous
#include <cuda_runtime.h>
#include <cuda_bf16.h>
#include <cuda_fp16.h>

#define NN 100000
#define EE 1600000
#define DIM 128
#define NH 4
#define HD 32

#define SCAN_B 512
#define SCAN_NB ((NN + SCAN_B - 1) / SCAN_B)   // 196

// ---------------- device scratch (static — no allocation allowed) ----------------
__device__ uint2 g_hh[(size_t)NN * 32];      // projected features, fp16 [N,128] (4 halves per uint2)
__device__ float g_esrc[NN * NH];            // per-node src logits [N,4]
__device__ float g_edst[NN * NH];            // per-node dst logits [N,4]
__device__ int   g_deg[NN];
__device__ int   g_cur[NN];
__device__ int   g_off[NN + 1];
__device__ int   g_part[SCAN_NB];            // per-block partial sums
__device__ int   g_partx[SCAN_NB];           // exclusive-scanned partials
__device__ int   g_edge_src[EE];             // src ids grouped by dst (CSR)
__device__ int   g_is64;

// ---------------- f32x2 helpers (Blackwell packed fp32 — PTX only) ----------------
__device__ __forceinline__ unsigned long long pk2(float s) {
    unsigned long long d;
    asm("mov.b64 %0, {%1, %1};" : "=l"(d) : "f"(s));
    return d;
}
__device__ __forceinline__ void fma2(unsigned long long& c, unsigned long long a,
                                     unsigned long long b) {
    asm("fma.rn.f32x2 %0, %1, %2, %0;" : "+l"(c) : "l"(a), "l"(b));
}
__device__ __forceinline__ float2 up2(unsigned long long v) {
    float2 r;
    asm("mov.b64 {%0, %1}, %2;" : "=f"(r.x), "=f"(r.y) : "l"(v));
    return r;
}

// ---------------- helpers ----------------
__device__ __forceinline__ int edge_idx(const void* p, int i, int is64) {
    return is64 ? (int)((const long long*)p)[i] : ((const int*)p)[i];
}

// detect whether src/dst are int64 (high 32-bit words all zero) or int32 — 1 warp, parallel
__global__ void k_detect(const void* src) {
    const unsigned* p = (const unsigned*)src;
    int lane = threadIdx.x;
    unsigned hi = p[2 * lane + 1] | p[2 * (lane + 32) + 1];
    unsigned b = __ballot_sync(0xffffffffu, hi == 0u);
    if (lane == 0) g_is64 = (b == 0xffffffffu) ? 1 : 0;
}

__global__ void k_init() {
    int i = blockIdx.x * blockDim.x + threadIdx.x;
    if (i < NN) { g_deg[i] = 0; g_cur[i] = 0; }
}

// ---------------- GEMM + fused logits ----------------
// h = feat @ fc_w.T  (N x 128 @ 128 x 128), then e_src/e_dst per row.
// block = 256 threads, 64 rows x 128 cols per block. Thread: 4 cols x 8 rows.
// Mainloop uses packed fma.rn.f32x2 (2x fp32 rate on sm_103a).
#define KC 32
__global__ void __launch_bounds__(256) k_gemm(const float* __restrict__ feat,
                                              const float* __restrict__ fc_w,
                                              const float* __restrict__ attn_src,
                                              const float* __restrict__ attn_dst) {
    __shared__ float wT[KC][132];   // [k][col], padded: row stride 528B (16B-mult)
    __shared__ float fT[KC][68];    // [k][row], row stride 272B (16B-mult)
    int tid = threadIdx.x;
    int tx = tid & 31;              // lane: cols 4*tx..4*tx+3
    int ty = tid >> 5;              // warp: rows ty*8..ty*8+7 within block
    int rbase = blockIdx.x * 64;

    unsigned long long A[16];       // 8 rows x 2 f32x2 pairs (cols 4tx..4tx+3)
#pragma unroll
    for (int r = 0; r < 16; r++) A[r] = 0ull;

    for (int k0 = 0; k0 < DIM; k0 += KC) {
        __syncthreads();
        // stage fc_w chunk transposed: 128 cols x 32 k
#pragma unroll
        for (int q = 0; q < 4; q++) {
            int id = tid + q * 256;           // 0..1023
            int c  = id >> 3;                 // 0..127
            int ks = (id & 7) * 4;            // 0..28
            float4 v = *(const float4*)&fc_w[c * DIM + k0 + ks];
            wT[ks + 0][c] = v.x; wT[ks + 1][c] = v.y;
            wT[ks + 2][c] = v.z; wT[ks + 3][c] = v.w;
        }
        // stage feat chunk transposed: 64 rows x 32 k
#pragma unroll
        for (int q = 0; q < 2; q++) {
            int id = tid + q * 256;           // 0..511
            int r  = id >> 3;                 // 0..63
            int ks = (id & 7) * 4;
            int gr = rbase + r;
            float4 v = make_float4(0.f, 0.f, 0.f, 0.f);
            if (gr < NN) v = *(const float4*)&feat[(size_t)gr * DIM + k0 + ks];
            fT[ks + 0][r] = v.x; fT[ks + 1][r] = v.y;
            fT[ks + 2][r] = v.z; fT[ks + 3][r] = v.w;
        }
        __syncthreads();
#pragma unroll
        for (int kk = 0; kk < KC; kk++) {
            ulonglong2 w2 = *(const ulonglong2*)&wT[kk][tx * 4];   // (wx,wy),(wz,ww)
            float4 fa = *(const float4*)&fT[kk][ty * 8];
            float4 fb = *(const float4*)&fT[kk][ty * 8 + 4];
#define STEP(r, S) { unsigned long long b = pk2(S); \
                     fma2(A[2*(r)], w2.x, b); fma2(A[2*(r)+1], w2.y, b); }
            STEP(0, fa.x) STEP(1, fa.y) STEP(2, fa.z) STEP(3, fa.w)
            STEP(4, fb.x) STEP(5, fb.y) STEP(6, fb.z) STEP(7, fb.w)
#undef STEP
        }
    }

    // attn vectors for this lane's 4 cols (all 4 cols belong to head tx>>3)
    float4 as4 = *(const float4*)&attn_src[tx * 4];
    float4 ad4 = *(const float4*)&attn_dst[tx * 4];
    int head = tx >> 3;

#pragma unroll
    for (int r = 0; r < 8; r++) {
        int gr = rbase + ty * 8 + r;
        float2 p0 = up2(A[2 * r]);
        float2 p1 = up2(A[2 * r + 1]);
        if (gr < NN) {
            __half2 ha = __floats2half2_rn(p0.x, p0.y);
            __half2 hb = __floats2half2_rn(p1.x, p1.y);
            uint2 u;
            u.x = *(const unsigned*)&ha;
            u.y = *(const unsigned*)&hb;
            g_hh[(size_t)gr * 32 + tx] = u;
        }
        // fused logits (fp32 accumulators): per-head dot across lanes 8h..8h+7
        float ps = p0.x * as4.x + p0.y * as4.y + p1.x * as4.z + p1.y * as4.w;
        float pd = p0.x * ad4.x + p0.y * ad4.y + p1.x * ad4.z + p1.y * ad4.w;
#pragma unroll
        for (int o = 1; o < 8; o <<= 1) {
            ps += __shfl_xor_sync(0xffffffffu, ps, o);
            pd += __shfl_xor_sync(0xffffffffu, pd, o);
        }
        if (gr < NN && (tx & 7) == 0) {
            g_esrc[gr * NH + head] = ps;
            g_edst[gr * NH + head] = pd;
        }
    }
}

// ---------------- CSR build ----------------
__global__ void k_hist(const void* __restrict__ dst) {
    int i = blockIdx.x * blockDim.x + threadIdx.x;
    if (i >= EE) return;
    int is64 = g_is64;
    int d = edge_idx(dst, i, is64);
    atomicAdd(&g_deg[d], 1);
}

// stage 1: per-block sums of g_deg
__global__ void __launch_bounds__(SCAN_B) k_scan1() {
    __shared__ int sm[SCAN_B];
    int t = threadIdx.x;
    int i = blockIdx.x * SCAN_B + t;
    sm[t] = (i < NN) ? g_deg[i] : 0;
    __syncthreads();
#pragma unroll
    for (int off = SCAN_B / 2; off > 0; off >>= 1) {
        if (t < off) sm[t] += sm[t + off];
        __syncthreads();
    }
    if (t == 0) g_part[blockIdx.x] = sm[0];
}

// stage 2: exclusive scan of SCAN_NB partials (one block)
__global__ void __launch_bounds__(256) k_scan2() {
    __shared__ int sm[256];
    int t = threadIdx.x;
    int v = (t < SCAN_NB) ? g_part[t] : 0;
    sm[t] = v;
    __syncthreads();
#pragma unroll
    for (int off = 1; off < 256; off <<= 1) {
        int x = (t >= off) ? sm[t - off] : 0;
        __syncthreads();
        sm[t] += x;
        __syncthreads();
    }
    if (t < SCAN_NB) g_partx[t] = sm[t] - v;   // exclusive
    if (t == 255) g_off[NN] = sm[255];          // total
}

// stage 3: per-block local scan + global offset -> g_off
__global__ void __launch_bounds__(SCAN_B) k_scan3() {
    __shared__ int sm[SCAN_B];
    int t = threadIdx.x;
    int i = blockIdx.x * SCAN_B + t;
    int v = (i < NN) ? g_deg[i] : 0;
    sm[t] = v;
    __syncthreads();
#pragma unroll
    for (int off = 1; off < SCAN_B; off <<= 1) {
        int x = (t >= off) ? sm[t - off] : 0;
        __syncthreads();
        sm[t] += x;
        __syncthreads();
    }
    if (i < NN) g_off[i] = g_partx[blockIdx.x] + sm[t] - v;   // exclusive
}

__global__ void k_scatter(const void* __restrict__ src, const void* __restrict__ dst) {
    int i = blockIdx.x * blockDim.x + threadIdx.x;
    if (i >= EE) return;
    int is64 = g_is64;
    int d = edge_idx(dst, i, is64);
    int s = edge_idx(src, i, is64);
    int pos = g_off[d] + atomicAdd(&g_cur[d], 1);
    g_edge_src[pos] = s;
}

// ---------------- softmax + aggregation: warp per dst node ----------------
__global__ void __launch_bounds__(256) k_agg(const float* __restrict__ feat,
                                             float* __restrict__ out) {
    int n = (blockIdx.x * blockDim.x + threadIdx.x) >> 5;
    int lane = threadIdx.x & 31;
    if (n >= NN) return;
    int beg = g_off[n], end = g_off[n + 1];
    float4 f4 = *(const float4*)&feat[(size_t)n * DIM + lane * 4];
    if (beg == end) {                 // no incoming edges: out = feat (residual)
        *(float4*)&out[(size_t)n * DIM + lane * 4] = f4;
        return;
    }
    float4 ed4 = *(const float4*)&g_edst[n * NH];

    // phase 1: sum of exp(leaky(e)) per head (no max-sub; |e| <~ 5, safe in fp32)
    float4 s4 = make_float4(0.f, 0.f, 0.f, 0.f);
    for (int i = beg + lane; i < end; i += 32) {
        int s = g_edge_src[i];
        float4 es = *(const float4*)&g_esrc[s * NH];
        float ex = es.x + ed4.x; ex = ex > 0.f ? ex : 0.2f * ex;
        float ey = es.y + ed4.y; ey = ey > 0.f ? ey : 0.2f * ey;
        float ez = es.z + ed4.z; ez = ez > 0.f ? ez : 0.2f * ez;
        float ew = es.w + ed4.w; ew = ew > 0.f ? ew : 0.2f * ew;
        s4.x += __expf(ex); s4.y += __expf(ey);
        s4.z += __expf(ez); s4.w += __expf(ew);
    }
#pragma unroll
    for (int o = 1; o < 32; o <<= 1) {
        s4.x += __shfl_xor_sync(0xffffffffu, s4.x, o);
        s4.y += __shfl_xor_sync(0xffffffffu, s4.y, o);
        s4.z += __shfl_xor_sync(0xffffffffu, s4.z, o);
        s4.w += __shfl_xor_sync(0xffffffffu, s4.w, o);
    }
    int head = lane >> 3;             // this lane's 4 dims all belong to one head
    float ssum = (head == 0) ? s4.x : (head == 1) ? s4.y : (head == 2) ? s4.z : s4.w;
    float edh  = (head == 0) ? ed4.x : (head == 1) ? ed4.y : (head == 2) ? ed4.z : ed4.w;
    float inv = 1.0f / ssum;

    // phase 2: gather fp16 h[src] weighted by unnormalized exp, 2-way unrolled for MLP
    float4 acc = make_float4(0.f, 0.f, 0.f, 0.f);
    const uint2* hh = g_hh;
    int i = beg;
    for (; i + 2 <= end; i += 2) {
        int s0 = g_edge_src[i];
        int s1 = g_edge_src[i + 1];
        float e0 = g_esrc[s0 * NH + head] + edh;
        float e1 = g_esrc[s1 * NH + head] + edh;
        uint2 u0 = hh[(size_t)s0 * 32 + lane];
        uint2 u1 = hh[(size_t)s1 * 32 + lane];
        e0 = e0 > 0.f ? e0 : 0.2f * e0;
        e1 = e1 > 0.f ? e1 : 0.2f * e1;
        float w0 = __expf(e0);
        float w1 = __expf(e1);
        float2 a0 = __half22float2(*(const __half2*)&u0.x);
        float2 b0 = __half22float2(*(const __half2*)&u0.y);
        float2 a1 = __half22float2(*(const __half2*)&u1.x);
        float2 b1 = __half22float2(*(const __half2*)&u1.y);
        acc.x += w0 * a0.x; acc.y += w0 * a0.y;
        acc.z += w0 * b0.x; acc.w += w0 * b0.y;
        acc.x += w1 * a1.x; acc.y += w1 * a1.y;
        acc.z += w1 * b1.x; acc.w += w1 * b1.y;
    }
    for (; i < end; i++) {
        int s = g_edge_src[i];
        float e = g_esrc[s * NH + head] + edh;
        e = e > 0.f ? e : 0.2f * e;
        float w = __expf(e);
        uint2 u = hh[(size_t)s * 32 + lane];
        float2 a = __half22float2(*(const __half2*)&u.x);
        float2 b = __half22float2(*(const __half2*)&u.y);
        acc.x += w * a.x; acc.y += w * a.y;
        acc.z += w * b.x; acc.w += w * b.y;
    }
    float4 o4;
    o4.x = acc.x * inv + f4.x;
    o4.y = acc.y * inv + f4.y;
    o4.z = acc.z * inv + f4.z;
    o4.w = acc.w * inv + f4.w;
    *(float4*)&out[(size_t)n * DIM + lane * 4] = o4;
}

// ---------------- launch ----------------
extern "C" void kernel_launch(void* const* d_in, const int* in_sizes, int n_in,
                              void* d_out, int out_size) {
    const float* feat     = (const float*)d_in[0];
    const float* fc_w     = (const float*)d_in[1];
    const float* attn_src = (const float*)d_in[2];
    const float* attn_dst = (const float*)d_in[3];
    const void*  src      = d_in[4];
    const void*  dst      = d_in[5];
    float* out = (float*)d_out;

    // one-time host-side stream/event setup (first call = correctness run, not captured)
    static cudaStream_t s2 = nullptr;
    static cudaEvent_t evA = nullptr, evB = nullptr;
    if (!s2) {
        cudaStreamCreate(&s2);
        cudaEventCreateWithFlags(&evA, cudaEventDisableTiming);
        cudaEventCreateWithFlags(&evB, cudaEventDisableTiming);
    }

    // fork: CSR build chain on s2 (depends only on src/dst), GEMM on main stream
    cudaEventRecord(evA, 0);
    cudaStreamWaitEvent(s2, evA, 0);

    k_detect<<<1, 32, 0, s2>>>(src);
    k_init<<<(NN + 255) / 256, 256, 0, s2>>>();
    k_hist<<<(EE + 255) / 256, 256, 0, s2>>>(dst);
    k_scan1<<<SCAN_NB, SCAN_B, 0, s2>>>();
    k_scan2<<<1, 256, 0, s2>>>();
    k_scan3<<<SCAN_NB, SCAN_B, 0, s2>>>();
    k_scatter<<<(EE + 255) / 256, 256, 0, s2>>>(src, dst);
    cudaEventRecord(evB, s2);

    k_gemm<<<(NN + 63) / 64, 256>>>(feat, fc_w, attn_src, attn_dst);

    // join, then aggregate
    cudaStreamWaitEvent(0, evB, 0);
    k_agg<<<(NN + 7) / 8, 256>>>(feat, out);
}